// round 8
// baseline (speedup 1.0000x reference)
#include <cuda_runtime.h>
#include <cuda_bf16.h>
#include <math.h>
#include <stdint.h>

#define B_  64
#define S_  2048
#define H_  512
#define M_  (B_ * S_)

// Fixed-point scales: x ~= s * q, q in [-16319, 16319] (15-bit), q = 128*hi + lo
#define SA_  (7.0f    / 16319.0f)
#define SB_  (0.25f   / 16319.0f)
#define INV_SA_ (16319.0f / 7.0f)
#define INV_SB_ (16319.0f / 0.25f)
#define C1_  (16384.0f * SA_ * SB_)   // weight of hi*hi term
#define C2_  (128.0f   * SA_ * SB_)   // weight of hi*lo + lo*hi terms

// ---------------- device scratch (no allocs allowed) ----------------
__device__ int8_t g_Ah[(size_t)M_ * H_];   // 64 MB enc hi limb
__device__ int8_t g_Al[(size_t)M_ * H_];   // 64 MB enc lo limb
__device__ int8_t g_Bh[H_ * H_];           // Wh^T hi [n][k]
__device__ int8_t g_Bl[H_ * H_];           // Wh^T lo [n][k]
__device__ float g_comb[B_ * H_];          // dec@Ws + bs + bh + bc
__device__ float g_epart[4 * M_];          // per-nc partial e sums

// ---------------- helpers ----------------
__device__ __forceinline__ uint32_t smem_u32(const void* p) {
    uint32_t a;
    asm("{ .reg .u64 t; cvta.to.shared.u64 t, %1; cvt.u32.u64 %0, t; }" : "=r"(a) : "l"(p));
    return a;
}
// accurate tanh: 2 MUFU, rel err ~1e-7, saturates correctly
__device__ __forceinline__ float tanh_acc(float x) {
    float e = __expf(2.0f * x);
    return 1.0f - __fdividef(2.0f, e + 1.0f);
}
__device__ __forceinline__ void ldsm4(uint32_t* r, uint32_t addr) {
    asm volatile("ldmatrix.sync.aligned.m8n8.x4.shared.b16 {%0,%1,%2,%3}, [%4];"
                 : "=r"(r[0]), "=r"(r[1]), "=r"(r[2]), "=r"(r[3]) : "r"(addr));
}
__device__ __forceinline__ void mma_s8(int* c, const uint32_t* a, uint32_t b0, uint32_t b1) {
    asm volatile(
        "mma.sync.aligned.m16n8k32.row.col.s32.s8.s8.s32 "
        "{%0,%1,%2,%3},{%4,%5,%6,%7},{%8,%9},{%0,%1,%2,%3};"
        : "+r"(c[0]), "+r"(c[1]), "+r"(c[2]), "+r"(c[3])
        : "r"(a[0]), "r"(a[1]), "r"(a[2]), "r"(a[3]), "r"(b0), "r"(b1));
}
__device__ __forceinline__ void cp16(uint32_t dst, const void* src) {
    asm volatile("cp.async.cg.shared.global [%0], [%1], 16;" :: "r"(dst), "l"(src));
}
// quantize to 15-bit, rounded split: hi in [-127,127], lo in [-64,63]
__device__ __forceinline__ void q15(float x, float invs, int& hi, int& lo) {
    int q = __float2int_rn(x * invs);
    q = max(-16319, min(16319, q));
    hi = (q + 64) >> 7;
    lo = q - (hi << 7);
}
__device__ __forceinline__ uint32_t pack4(int a, int b, int c, int d) {
    return (a & 0xFF) | ((b & 0xFF) << 8) | ((c & 0xFF) << 16) | ((d & 0xFF) << 24);
}

// ---------------------------------------------------------------------------
// Pack A: enc fp32 -> g_Ah / g_Al (int8 limbs)
// ---------------------------------------------------------------------------
__global__ void apack_kernel(const float* __restrict__ A)
{
    const size_t i = (size_t)blockIdx.x * 256 + threadIdx.x;  // float4 index
    const float4 v = ((const float4*)A)[i];
    int h0, l0, h1, l1, h2, l2, h3, l3;
    q15(v.x, INV_SA_, h0, l0);
    q15(v.y, INV_SA_, h1, l1);
    q15(v.z, INV_SA_, h2, l2);
    q15(v.w, INV_SA_, h3, l3);
    ((uint32_t*)g_Ah)[i] = pack4(h0, h1, h2, h3);
    ((uint32_t*)g_Al)[i] = pack4(l0, l1, l2, l3);
}

// ---------------------------------------------------------------------------
// Pack B: Wh [k][n] fp32 -> g_Bh / g_Bl [n][k] int8 limbs (transpose)
// ---------------------------------------------------------------------------
__global__ void bpack_kernel(const float* __restrict__ Wh)
{
    const int n  = blockIdx.x;              // 0..511
    const int k4 = threadIdx.x * 4;         // 128 threads x 4 k
    int h[4], l[4];
    #pragma unroll
    for (int j = 0; j < 4; ++j)
        q15(Wh[(size_t)(k4 + j) * H_ + n], INV_SB_, h[j], l[j]);
    *(uint32_t*)(g_Bh + (size_t)n * H_ + k4) = pack4(h[0], h[1], h[2], h[3]);
    *(uint32_t*)(g_Bl + (size_t)n * H_ + k4) = pack4(l[0], l[1], l[2], l[3]);
}

// ---------------------------------------------------------------------------
// comb[b][n] = dec[b] @ Ws[:,n] + bs + bh + bc
// ---------------------------------------------------------------------------
__global__ void dec_comb_kernel(const float* __restrict__ dec,
                                const float* __restrict__ Ws,
                                const float* __restrict__ bs,
                                const float* __restrict__ bh,
                                const float* __restrict__ bc)
{
    const int b  = blockIdx.x;
    const int nh = blockIdx.y;
    const int tid = threadIdx.x;
    __shared__ float dh[H_];
    __shared__ float red[4][64];

    dh[tid]       = dec[b * H_ + tid];
    dh[tid + 256] = dec[b * H_ + tid + 256];
    __syncthreads();

    const int nl = tid & 63;
    const int n  = nh * 64 + nl;
    const int ks = tid >> 6;
    float acc = 0.f;
    #pragma unroll 8
    for (int h = ks * 128; h < ks * 128 + 128; ++h)
        acc = fmaf(dh[h], Ws[(size_t)h * H_ + n], acc);
    red[ks][nl] = acc;
    __syncthreads();
    if (ks == 0) {
        float s = red[0][nl] + red[1][nl] + red[2][nl] + red[3][nl];
        g_comb[b * H_ + n] = s + bs[n] + bh[n] + bc[n];
    }
}

// ---------------------------------------------------------------------------
// Main: 128x128x512 IMMA GEMM (3-term int8 split) + fused tanh/v-dot epilogue
// grid (4 nc, 1024 m-tiles), 512 threads = 16 warps (warpM 0..3 x warpN 0..3)
// k-chunk = 64 int8 (64 bytes/row), 8 chunks, double-buffered cp.async.
// ---------------------------------------------------------------------------
#define PITCH     80                      // 64B data + 16B pad -> ldmatrix conflict-free
#define MAT_BYTES (128 * PITCH)           // 10240
#define STAGE_BYTES (4 * MAT_BYTES)       // 40960 (Ah|Al|Bh|Bl)
#define OFF_COMB  (2 * STAGE_BYTES)       // 81920
#define OFF_WC    (OFF_COMB + 512)
#define OFF_VW    (OFF_WC + 512)
#define OFF_ERED  (OFF_VW + 512)          // 83456
#define SMEM_DYN  (OFF_ERED + 128 * 16 * 4)  // 91648

__global__ __launch_bounds__(512, 1)
void attn_imma_kernel(const float* __restrict__ cov,
                      const float* __restrict__ Wc,
                      const float* __restrict__ v_w)
{
    extern __shared__ char sm[];
    const uint32_t sbase = smem_u32(sm);
    const int tid  = threadIdx.x;
    const int wid  = tid >> 5;
    const int lane = tid & 31;
    const int nc     = blockIdx.x;          // 0..3 (fast-varying: A-tile L2 reuse)
    const int mBase  = blockIdx.y * 128;
    const int ncBase = nc * 128;
    const int b      = mBase >> 11;

    // epilogue constants for this n-chunk
    if (tid < 128) {
        ((float*)(sm + OFF_COMB))[tid] = g_comb[b * H_ + ncBase + tid];
        ((float*)(sm + OFF_WC))[tid]   = Wc[ncBase + tid];
        ((float*)(sm + OFF_VW))[tid]   = v_w[ncBase + tid];
    }

    // per-thread cp.async mapping: 2048 16B transfers/chunk, 4 per thread
    const char* srcs[4];
    uint32_t dsts[4];
    #pragma unroll
    for (int p = 0; p < 4; ++p) {
        const int idx = p * 512 + tid;
        const int mat = idx >> 9;          // 0:Ah 1:Al 2:Bh 3:Bl
        const int r   = (idx >> 2) & 127;
        const int cc  = idx & 3;
        const int8_t* g;
        if      (mat == 0) g = g_Ah + (size_t)(mBase + r) * H_;
        else if (mat == 1) g = g_Al + (size_t)(mBase + r) * H_;
        else if (mat == 2) g = g_Bh + (size_t)(ncBase + r) * H_;
        else               g = g_Bl + (size_t)(ncBase + r) * H_;
        srcs[p] = (const char*)(g + cc * 16);
        dsts[p] = sbase + mat * MAT_BYTES + r * PITCH + cc * 16;
    }

    const int warpM = wid >> 2;            // 0..3 -> 32 rows
    const int warpN = wid & 3;             // 0..3 -> 32 cols

    // ldmatrix offsets (relative to matrix base; add stage offset later)
    uint32_t offA[2][2], offB[2][2];
    {
        const int rowA = warpM * 32 + (lane & 7) + ((lane >> 3) & 1) * 8;
        const int cA   = (lane >> 4);                   // 0..1 (16B k-halves)
        #pragma unroll
        for (int mI = 0; mI < 2; ++mI)
            #pragma unroll
            for (int s = 0; s < 2; ++s)
                offA[mI][s] = (uint32_t)((rowA + mI * 16) * PITCH + (s * 2 + cA) * 16);
        const int rowB = warpN * 32 + (lane & 7) + ((lane & 16) ? 8 : 0);
        const int cB   = (lane >> 3) & 1;
        #pragma unroll
        for (int p = 0; p < 2; ++p)
            #pragma unroll
            for (int s = 0; s < 2; ++s)
                offB[p][s] = (uint32_t)((rowB + p * 16) * PITCH + (s * 2 + cB) * 16);
    }

    int acc1[2][4][4];   // hi*hi
    int acc2[2][4][4];   // hi*lo + lo*hi
    #pragma unroll
    for (int i = 0; i < 2; ++i)
        #pragma unroll
        for (int j = 0; j < 4; ++j)
            #pragma unroll
            for (int q = 0; q < 4; ++q) { acc1[i][j][q] = 0; acc2[i][j][q] = 0; }

    // prefetch chunk 0
    #pragma unroll
    for (int p = 0; p < 4; ++p) cp16(dsts[p], srcs[p]);
    asm volatile("cp.async.commit_group;" ::: "memory");

    #pragma unroll 1
    for (int c = 0; c < 8; ++c) {
        if (c < 7) {
            const uint32_t soff = ((c + 1) & 1) * STAGE_BYTES;
            #pragma unroll
            for (int p = 0; p < 4; ++p)
                cp16(dsts[p] + soff, srcs[p] + (c + 1) * 64);
            asm volatile("cp.async.commit_group;" ::: "memory");
            asm volatile("cp.async.wait_group 1;" ::: "memory");
        } else {
            asm volatile("cp.async.wait_group 0;" ::: "memory");
        }
        __syncthreads();

        const uint32_t st  = (c & 1) * STAGE_BYTES;
        const uint32_t ahb = sbase + st;
        const uint32_t alb = ahb + MAT_BYTES;
        const uint32_t bhb = ahb + 2 * MAT_BYTES;
        const uint32_t blb = ahb + 3 * MAT_BYTES;

        #pragma unroll
        for (int s = 0; s < 2; ++s) {      // each s = 32 int8 k
            uint32_t AH[2][4], AL[2][4], BH[2][4], BL[2][4];
            #pragma unroll
            for (int mI = 0; mI < 2; ++mI) ldsm4(AH[mI], ahb + offA[mI][s]);
            #pragma unroll
            for (int p = 0; p < 2; ++p)    ldsm4(BH[p], bhb + offB[p][s]);
            // term 1: hi*hi -> acc1
            #pragma unroll
            for (int mI = 0; mI < 2; ++mI)
                #pragma unroll
                for (int nI = 0; nI < 4; ++nI)
                    mma_s8(acc1[mI][nI], AH[mI], BH[nI >> 1][(nI & 1) * 2], BH[nI >> 1][(nI & 1) * 2 + 1]);
            #pragma unroll
            for (int p = 0; p < 2; ++p)    ldsm4(BL[p], blb + offB[p][s]);
            // term 2: hi*lo -> acc2
            #pragma unroll
            for (int mI = 0; mI < 2; ++mI)
                #pragma unroll
                for (int nI = 0; nI < 4; ++nI)
                    mma_s8(acc2[mI][nI], AH[mI], BL[nI >> 1][(nI & 1) * 2], BL[nI >> 1][(nI & 1) * 2 + 1]);
            #pragma unroll
            for (int mI = 0; mI < 2; ++mI) ldsm4(AL[mI], alb + offA[mI][s]);
            // term 3: lo*hi -> acc2
            #pragma unroll
            for (int mI = 0; mI < 2; ++mI)
                #pragma unroll
                for (int nI = 0; nI < 4; ++nI)
                    mma_s8(acc2[mI][nI], AL[mI], BH[nI >> 1][(nI & 1) * 2], BH[nI >> 1][(nI & 1) * 2 + 1]);
        }
        __syncthreads();
    }

    // ---- fused epilogue: dequant + tanh + v-dot, reduce across 16 col-threads ----
    const float* sComb = (const float*)(sm + OFF_COMB);
    const float* sWc   = (const float*)(sm + OFF_WC);
    const float* sVw   = (const float*)(sm + OFF_VW);
    float* ered = (float*)(sm + OFF_ERED);
    const int col = warpN * 4 + (lane & 3);

    #pragma unroll
    for (int mI = 0; mI < 2; ++mI) {
        const int mlo = warpM * 32 + mI * 16 + (lane >> 2);
        const float covlo = cov[mBase + mlo];
        const float covhi = cov[mBase + mlo + 8];
        float elo = 0.f, ehi = 0.f;
        #pragma unroll
        for (int nI = 0; nI < 4; ++nI) {
            #pragma unroll
            for (int t = 0; t < 2; ++t) {
                const int n = warpN * 32 + nI * 8 + (lane & 3) * 2 + t;
                const float cb = sComb[n], wc = sWc[n], vw = sVw[n];
                const float g0 = fmaf((float)acc1[mI][nI][t],     C1_, (float)acc2[mI][nI][t]     * C2_);
                const float g1 = fmaf((float)acc1[mI][nI][t + 2], C1_, (float)acc2[mI][nI][t + 2] * C2_);
                elo = fmaf(vw, tanh_acc(g0 + cb + covlo * wc), elo);
                ehi = fmaf(vw, tanh_acc(g1 + cb + covhi * wc), ehi);
            }
        }
        ered[mlo * 16 + col]       = elo;
        ered[(mlo + 8) * 16 + col] = ehi;
    }
    __syncthreads();
    if (tid < 128) {
        float s = 0.f;
        #pragma unroll
        for (int t = 0; t < 16; ++t) s += ered[tid * 16 + t];
        g_epart[nc * M_ + mBase + tid] = s;
    }
}

// ---------------------------------------------------------------------------
// Softmax over S=2048 per batch + coverage update (v_b shift-invariant)
// ---------------------------------------------------------------------------
__global__ __launch_bounds__(256)
void softmax_kernel(const float* __restrict__ cov, float* __restrict__ out)
{
    const int b   = blockIdx.x;
    const int tid = threadIdx.x;
    __shared__ float red[256];

    float local[8];
    float mx = -INFINITY;
    #pragma unroll
    for (int i = 0; i < 8; ++i) {
        const int idx = b * S_ + tid + i * 256;
        local[i] = g_epart[idx] + g_epart[M_ + idx] + g_epart[2 * M_ + idx] + g_epart[3 * M_ + idx];
        mx = fmaxf(mx, local[i]);
    }
    red[tid] = mx;
    __syncthreads();
    for (int s = 128; s > 0; s >>= 1) {
        if (tid < s) red[tid] = fmaxf(red[tid], red[tid + s]);
        __syncthreads();
    }
    const float m = red[0];
    __syncthreads();

    float sum = 0.f;
    #pragma unroll
    for (int i = 0; i < 8; ++i) {
        local[i] = __expf(local[i] - m);
        sum += local[i];
    }
    red[tid] = sum;
    __syncthreads();
    for (int s = 128; s > 0; s >>= 1) {
        if (tid < s) red[tid] += red[tid + s];
        __syncthreads();
    }
    const float inv = 1.0f / red[0];

    #pragma unroll
    for (int i = 0; i < 8; ++i) {
        const int idx = b * S_ + tid + i * 256;
        const float a = local[i] * inv;
        out[idx]      = a;
        out[M_ + idx] = cov[idx] + a;
    }
}

// ---------------------------------------------------------------------------
extern "C" void kernel_launch(void* const* d_in, const int* in_sizes, int n_in,
                              void* d_out, int out_size)
{
    const float* enc = (const float*)d_in[0];
    const float* dec = (const float*)d_in[1];
    const float* cov = (const float*)d_in[2];
    const float* Wh  = (const float*)d_in[3];
    const float* bh  = (const float*)d_in[4];
    const float* Ws  = (const float*)d_in[5];
    const float* bs  = (const float*)d_in[6];
    const float* Wc  = (const float*)d_in[7];
    const float* bc  = (const float*)d_in[8];
    const float* v_w = (const float*)d_in[9];
    float* out = (float*)d_out;

    cudaFuncSetAttribute(attn_imma_kernel,
                         cudaFuncAttributeMaxDynamicSharedMemorySize, SMEM_DYN);

    apack_kernel<<<M_ * H_ / 4 / 256, 256>>>(enc);
    bpack_kernel<<<H_, 128>>>(Wh);
    dec_comb_kernel<<<dim3(B_, 8), 256>>>(dec, Ws, bs, bh, bc);
    attn_imma_kernel<<<dim3(4, M_ / 128), 512, SMEM_DYN>>>(cov, Wc, v_w);
    softmax_kernel<<<B_, 256>>>(cov, out);
}

// round 9
// speedup vs baseline: 3.6367x; 3.6367x over previous
#include <cuda_runtime.h>
#include <cuda_fp16.h>
#include <math.h>
#include <stdint.h>

#define B_  64
#define S_  2048
#define H_  512
#define M_  (B_ * S_)

// ---------------- device scratch (no allocs allowed) ----------------
__device__ __half g_Af[(size_t)M_ * H_];   // 128 MB enc fp16
__device__ __half g_Bf[H_ * H_];           // Wh^T fp16 [n][k]
__device__ float g_comb[B_ * H_];          // dec@Ws + bs + bh + bc
__device__ float g_epart[4 * M_];          // per-nc partial e sums

// ---------------- helpers ----------------
__device__ __forceinline__ uint32_t smem_u32(const void* p) {
    uint32_t a;
    asm("{ .reg .u64 t; cvta.to.shared.u64 t, %1; cvt.u32.u64 %0, t; }" : "=r"(a) : "l"(p));
    return a;
}
// accurate tanh: 2 MUFU, rel err ~1e-7, saturates correctly
__device__ __forceinline__ float tanh_acc(float x) {
    float e = __expf(2.0f * x);
    return 1.0f - __fdividef(2.0f, e + 1.0f);
}
__device__ __forceinline__ void ldsm4(uint32_t* r, uint32_t addr) {
    asm volatile("ldmatrix.sync.aligned.m8n8.x4.shared.b16 {%0,%1,%2,%3}, [%4];"
                 : "=r"(r[0]), "=r"(r[1]), "=r"(r[2]), "=r"(r[3]) : "r"(addr));
}
__device__ __forceinline__ void mma_f16(float* c, const uint32_t* a, uint32_t b0, uint32_t b1) {
    asm volatile(
        "mma.sync.aligned.m16n8k16.row.col.f32.f16.f16.f32 "
        "{%0,%1,%2,%3},{%4,%5,%6,%7},{%8,%9},{%0,%1,%2,%3};"
        : "+f"(c[0]), "+f"(c[1]), "+f"(c[2]), "+f"(c[3])
        : "r"(a[0]), "r"(a[1]), "r"(a[2]), "r"(a[3]), "r"(b0), "r"(b1));
}
__device__ __forceinline__ void cp16(uint32_t dst, const void* src) {
    asm volatile("cp.async.cg.shared.global [%0], [%1], 16;" :: "r"(dst), "l"(src));
}

// ---------------------------------------------------------------------------
// Pack A: enc fp32 -> g_Af fp16
// ---------------------------------------------------------------------------
__global__ void apack_kernel(const float* __restrict__ A)
{
    const size_t i = (size_t)blockIdx.x * 256 + threadIdx.x;  // float4 index
    const float4 v = ((const float4*)A)[i];
    __half2 lo = __floats2half2_rn(v.x, v.y);
    __half2 hi = __floats2half2_rn(v.z, v.w);
    ((uint2*)g_Af)[i] = make_uint2(*(uint32_t*)&lo, *(uint32_t*)&hi);
}

// ---------------------------------------------------------------------------
// Pack B: Wh [k][n] fp32 -> g_Bf [n][k] fp16 (transpose)
// ---------------------------------------------------------------------------
__global__ void bpack_kernel(const float* __restrict__ Wh)
{
    const int n  = blockIdx.x;              // 0..511
    const int k4 = threadIdx.x * 4;         // 128 threads x 4 k
    __half2 lo = __floats2half2_rn(Wh[(size_t)(k4 + 0) * H_ + n], Wh[(size_t)(k4 + 1) * H_ + n]);
    __half2 hi = __floats2half2_rn(Wh[(size_t)(k4 + 2) * H_ + n], Wh[(size_t)(k4 + 3) * H_ + n]);
    *(uint2*)(g_Bf + (size_t)n * H_ + k4) = make_uint2(*(uint32_t*)&lo, *(uint32_t*)&hi);
}

// ---------------------------------------------------------------------------
// comb[b][n] = dec[b] @ Ws[:,n] + bs + bh + bc
// ---------------------------------------------------------------------------
__global__ void dec_comb_kernel(const float* __restrict__ dec,
                                const float* __restrict__ Ws,
                                const float* __restrict__ bs,
                                const float* __restrict__ bh,
                                const float* __restrict__ bc)
{
    const int b  = blockIdx.x;
    const int nh = blockIdx.y;
    const int tid = threadIdx.x;
    __shared__ float dh[H_];
    __shared__ float red[4][64];

    dh[tid]       = dec[b * H_ + tid];
    dh[tid + 256] = dec[b * H_ + tid + 256];
    __syncthreads();

    const int nl = tid & 63;
    const int n  = nh * 64 + nl;
    const int ks = tid >> 6;
    float acc = 0.f;
    #pragma unroll 8
    for (int h = ks * 128; h < ks * 128 + 128; ++h)
        acc = fmaf(dh[h], Ws[(size_t)h * H_ + n], acc);
    red[ks][nl] = acc;
    __syncthreads();
    if (ks == 0) {
        float s = red[0][nl] + red[1][nl] + red[2][nl] + red[3][nl];
        g_comb[b * H_ + n] = s + bs[n] + bh[n] + bc[n];
    }
}

// ---------------------------------------------------------------------------
// Main: 128x128x512 fp16 HMMA GEMM (single term) + fused tanh/v-dot epilogue
// grid (4 nc, 1024 m-tiles), 512 threads = 16 warps (warpM 0..3 x warpN 0..3)
// ---------------------------------------------------------------------------
#define PITCH     80                      // 64B data + 16B pad -> ldmatrix conflict-free
#define MAT_BYTES (128 * PITCH)           // 10240
#define STAGE_BYTES (2 * MAT_BYTES)       // 20480 (A|B)
#define OFF_COMB  (2 * STAGE_BYTES)       // 40960
#define OFF_WC    (OFF_COMB + 512)
#define OFF_VW    (OFF_WC + 512)
#define OFF_ERED  (OFF_VW + 512)          // 42496
#define SMEM_DYN  (OFF_ERED + 128 * 16 * 4)  // 50688

__global__ __launch_bounds__(512, 1)
void attn_hmma_kernel(const float* __restrict__ cov,
                      const float* __restrict__ Wc,
                      const float* __restrict__ v_w)
{
    extern __shared__ char sm[];
    const uint32_t sbase = smem_u32(sm);
    const int tid  = threadIdx.x;
    const int wid  = tid >> 5;
    const int lane = tid & 31;
    const int nc     = blockIdx.x;          // 0..3 (fast-varying: A-tile L2 reuse)
    const int mBase  = blockIdx.y * 128;
    const int ncBase = nc * 128;
    const int b      = mBase >> 11;

    // epilogue constants for this n-chunk
    if (tid < 128) {
        ((float*)(sm + OFF_COMB))[tid] = g_comb[b * H_ + ncBase + tid];
        ((float*)(sm + OFF_WC))[tid]   = Wc[ncBase + tid];
        ((float*)(sm + OFF_VW))[tid]   = v_w[ncBase + tid];
    }

    // per-thread cp.async mapping: 1024 16B transfers/chunk, 2 per thread
    const char* srcs[2];
    uint32_t dsts[2];
    #pragma unroll
    for (int p = 0; p < 2; ++p) {
        const int idx = p * 512 + tid;
        const int mat = idx >> 9;          // 0:A 1:B
        const int r   = (idx >> 2) & 127;
        const int cc  = idx & 3;
        const __half* g = (mat == 0) ? (g_Af + (size_t)(mBase + r) * H_)
                                     : (g_Bf + (size_t)(ncBase + r) * H_);
        srcs[p] = (const char*)(g + cc * 8);
        dsts[p] = sbase + mat * MAT_BYTES + r * PITCH + cc * 16;
    }

    const int warpM = wid >> 2;            // 0..3 -> 32 rows
    const int warpN = wid & 3;             // 0..3 -> 32 cols

    // ldmatrix offsets (relative to matrix base; add stage offset later)
    uint32_t offA[2][2], offB[2][2];
    {
        const int rowA = warpM * 32 + (lane & 7) + ((lane >> 3) & 1) * 8;
        const int cA   = (lane >> 4);                   // 0..1
        #pragma unroll
        for (int mI = 0; mI < 2; ++mI)
            #pragma unroll
            for (int s = 0; s < 2; ++s)
                offA[mI][s] = (uint32_t)((rowA + mI * 16) * PITCH + (s * 2 + cA) * 16);
        const int rowB = warpN * 32 + (lane & 7) + ((lane & 16) ? 8 : 0);
        const int cB   = (lane >> 3) & 1;
        #pragma unroll
        for (int p = 0; p < 2; ++p)
            #pragma unroll
            for (int s = 0; s < 2; ++s)
                offB[p][s] = (uint32_t)((rowB + p * 16) * PITCH + (s * 2 + cB) * 16);
    }

    float acc[2][4][4];
    #pragma unroll
    for (int i = 0; i < 2; ++i)
        #pragma unroll
        for (int j = 0; j < 4; ++j)
            #pragma unroll
            for (int q = 0; q < 4; ++q) acc[i][j][q] = 0.f;

    // prefetch chunk 0
    #pragma unroll
    for (int p = 0; p < 2; ++p) cp16(dsts[p], srcs[p]);
    asm volatile("cp.async.commit_group;" ::: "memory");

    #pragma unroll 1
    for (int c = 0; c < 16; ++c) {
        if (c < 15) {
            const uint32_t soff = ((c + 1) & 1) * STAGE_BYTES;
            #pragma unroll
            for (int p = 0; p < 2; ++p)
                cp16(dsts[p] + soff, srcs[p] + (c + 1) * 64);
            asm volatile("cp.async.commit_group;" ::: "memory");
            asm volatile("cp.async.wait_group 1;" ::: "memory");
        } else {
            asm volatile("cp.async.wait_group 0;" ::: "memory");
        }
        __syncthreads();

        const uint32_t st = (c & 1) * STAGE_BYTES;
        const uint32_t ab = sbase + st;
        const uint32_t bb = ab + MAT_BYTES;

        #pragma unroll
        for (int s = 0; s < 2; ++s) {      // each s = 16 k
            uint32_t Af[2][4], Bf[2][4];
            #pragma unroll
            for (int mI = 0; mI < 2; ++mI) ldsm4(Af[mI], ab + offA[mI][s]);
            #pragma unroll
            for (int p = 0; p < 2; ++p)    ldsm4(Bf[p], bb + offB[p][s]);
            #pragma unroll
            for (int mI = 0; mI < 2; ++mI)
                #pragma unroll
                for (int nI = 0; nI < 4; ++nI)
                    mma_f16(acc[mI][nI], Af[mI], Bf[nI >> 1][(nI & 1) * 2], Bf[nI >> 1][(nI & 1) * 2 + 1]);
        }
        __syncthreads();
    }

    // ---- fused epilogue: tanh + v-dot, reduce across 16 column-threads ----
    const float* sComb = (const float*)(sm + OFF_COMB);
    const float* sWc   = (const float*)(sm + OFF_WC);
    const float* sVw   = (const float*)(sm + OFF_VW);
    float* ered = (float*)(sm + OFF_ERED);
    const int col = warpN * 4 + (lane & 3);

    #pragma unroll
    for (int mI = 0; mI < 2; ++mI) {
        const int mlo = warpM * 32 + mI * 16 + (lane >> 2);
        const float covlo = cov[mBase + mlo];
        const float covhi = cov[mBase + mlo + 8];
        float elo = 0.f, ehi = 0.f;
        #pragma unroll
        for (int nI = 0; nI < 4; ++nI) {
            #pragma unroll
            for (int t = 0; t < 2; ++t) {
                const int n = warpN * 32 + nI * 8 + (lane & 3) * 2 + t;
                const float cb = sComb[n], wc = sWc[n], vw = sVw[n];
                elo = fmaf(vw, tanh_acc(acc[mI][nI][t]     + cb + covlo * wc), elo);
                ehi = fmaf(vw, tanh_acc(acc[mI][nI][t + 2] + cb + covhi * wc), ehi);
            }
        }
        ered[mlo * 16 + col]       = elo;
        ered[(mlo + 8) * 16 + col] = ehi;
    }
    __syncthreads();
    if (tid < 128) {
        float s = 0.f;
        #pragma unroll
        for (int t = 0; t < 16; ++t) s += ered[tid * 16 + t];
        g_epart[nc * M_ + mBase + tid] = s;
    }
}

// ---------------------------------------------------------------------------
// Softmax over S=2048 per batch + coverage update (v_b shift-invariant)
// ---------------------------------------------------------------------------
__global__ __launch_bounds__(256)
void softmax_kernel(const float* __restrict__ cov, float* __restrict__ out)
{
    const int b   = blockIdx.x;
    const int tid = threadIdx.x;
    __shared__ float red[256];

    float local[8];
    float mx = -INFINITY;
    #pragma unroll
    for (int i = 0; i < 8; ++i) {
        const int idx = b * S_ + tid + i * 256;
        local[i] = g_epart[idx] + g_epart[M_ + idx] + g_epart[2 * M_ + idx] + g_epart[3 * M_ + idx];
        mx = fmaxf(mx, local[i]);
    }
    red[tid] = mx;
    __syncthreads();
    for (int s = 128; s > 0; s >>= 1) {
        if (tid < s) red[tid] = fmaxf(red[tid], red[tid + s]);
        __syncthreads();
    }
    const float m = red[0];
    __syncthreads();

    float sum = 0.f;
    #pragma unroll
    for (int i = 0; i < 8; ++i) {
        local[i] = __expf(local[i] - m);
        sum += local[i];
    }
    red[tid] = sum;
    __syncthreads();
    for (int s = 128; s > 0; s >>= 1) {
        if (tid < s) red[tid] += red[tid + s];
        __syncthreads();
    }
    const float inv = 1.0f / red[0];

    #pragma unroll
    for (int i = 0; i < 8; ++i) {
        const int idx = b * S_ + tid + i * 256;
        const float a = local[i] * inv;
        out[idx]      = a;
        out[M_ + idx] = cov[idx] + a;
    }
}

// ---------------------------------------------------------------------------
extern "C" void kernel_launch(void* const* d_in, const int* in_sizes, int n_in,
                              void* d_out, int out_size)
{
    const float* enc = (const float*)d_in[0];
    const float* dec = (const float*)d_in[1];
    const float* cov = (const float*)d_in[2];
    const float* Wh  = (const float*)d_in[3];
    const float* bh  = (const float*)d_in[4];
    const float* Ws  = (const float*)d_in[5];
    const float* bs  = (const float*)d_in[6];
    const float* Wc  = (const float*)d_in[7];
    const float* bc  = (const float*)d_in[8];
    const float* v_w = (const float*)d_in[9];
    float* out = (float*)d_out;

    cudaFuncSetAttribute(attn_hmma_kernel,
                         cudaFuncAttributeMaxDynamicSharedMemorySize, SMEM_DYN);

    apack_kernel<<<M_ * H_ / 4 / 256, 256>>>(enc);
    bpack_kernel<<<H_, 128>>>(Wh);
    dec_comb_kernel<<<dim3(B_, 8), 256>>>(dec, Ws, bs, bh, bc);
    attn_hmma_kernel<<<dim3(4, M_ / 128), 512, SMEM_DYN>>>(cov, Wc, v_w);
    softmax_kernel<<<B_, 256>>>(cov, out);
}

// round 10
// speedup vs baseline: 5.6054x; 1.5414x over previous
#include <cuda_runtime.h>
#include <cuda_fp16.h>
#include <math.h>
#include <stdint.h>

#define B_  64
#define S_  2048
#define H_  512
#define M_  (B_ * S_)

// ---------------- device scratch (no allocs allowed) ----------------
__device__ __half g_Af[(size_t)M_ * H_];   // 128 MB enc fp16
__device__ __half g_Bf[H_ * H_];           // Wh^T fp16 [n][k]
__device__ float g_comb[B_ * H_];          // dec@Ws + bs + bh + bc
__device__ float g_epart[4 * M_];          // per-nc partial e sums

// ---------------- helpers ----------------
__device__ __forceinline__ uint32_t smem_u32(const void* p) {
    uint32_t a;
    asm("{ .reg .u64 t; cvta.to.shared.u64 t, %1; cvt.u32.u64 %0, t; }" : "=r"(a) : "l"(p));
    return a;
}
// accurate tanh: 2 MUFU, rel err ~1e-7, saturates correctly
__device__ __forceinline__ float tanh_acc(float x) {
    float e = __expf(2.0f * x);
    return 1.0f - __fdividef(2.0f, e + 1.0f);
}
__device__ __forceinline__ void ldsm4(uint32_t* r, uint32_t addr) {
    asm volatile("ldmatrix.sync.aligned.m8n8.x4.shared.b16 {%0,%1,%2,%3}, [%4];"
                 : "=r"(r[0]), "=r"(r[1]), "=r"(r[2]), "=r"(r[3]) : "r"(addr));
}
__device__ __forceinline__ void mma_f16(float* c, const uint32_t* a, uint32_t b0, uint32_t b1) {
    asm volatile(
        "mma.sync.aligned.m16n8k16.row.col.f32.f16.f16.f32 "
        "{%0,%1,%2,%3},{%4,%5,%6,%7},{%8,%9},{%0,%1,%2,%3};"
        : "+f"(c[0]), "+f"(c[1]), "+f"(c[2]), "+f"(c[3])
        : "r"(a[0]), "r"(a[1]), "r"(a[2]), "r"(a[3]), "r"(b0), "r"(b1));
}
__device__ __forceinline__ void cp16(uint32_t dst, const void* src) {
    asm volatile("cp.async.cg.shared.global [%0], [%1], 16;" :: "r"(dst), "l"(src));
}

// ---------------------------------------------------------------------------
// Pack A: enc fp32 -> g_Af fp16
// ---------------------------------------------------------------------------
__global__ void apack_kernel(const float* __restrict__ A)
{
    const size_t i = (size_t)blockIdx.x * 256 + threadIdx.x;  // float4 index
    const float4 v = ((const float4*)A)[i];
    __half2 lo = __floats2half2_rn(v.x, v.y);
    __half2 hi = __floats2half2_rn(v.z, v.w);
    ((uint2*)g_Af)[i] = make_uint2(*(uint32_t*)&lo, *(uint32_t*)&hi);
}

// ---------------------------------------------------------------------------
// Pack B: Wh [k][n] fp32 -> g_Bf [n][k] fp16 (transpose)
// ---------------------------------------------------------------------------
__global__ void bpack_kernel(const float* __restrict__ Wh)
{
    const int n  = blockIdx.x;              // 0..511
    const int k4 = threadIdx.x * 4;         // 128 threads x 4 k
    __half2 lo = __floats2half2_rn(Wh[(size_t)(k4 + 0) * H_ + n], Wh[(size_t)(k4 + 1) * H_ + n]);
    __half2 hi = __floats2half2_rn(Wh[(size_t)(k4 + 2) * H_ + n], Wh[(size_t)(k4 + 3) * H_ + n]);
    *(uint2*)(g_Bf + (size_t)n * H_ + k4) = make_uint2(*(uint32_t*)&lo, *(uint32_t*)&hi);
}

// ---------------------------------------------------------------------------
// comb[b][n] = dec[b] @ Ws[:,n] + bs + bh + bc
// ---------------------------------------------------------------------------
__global__ void dec_comb_kernel(const float* __restrict__ dec,
                                const float* __restrict__ Ws,
                                const float* __restrict__ bs,
                                const float* __restrict__ bh,
                                const float* __restrict__ bc)
{
    const int b  = blockIdx.x;
    const int nh = blockIdx.y;
    const int tid = threadIdx.x;
    __shared__ float dh[H_];
    __shared__ float red[4][64];

    dh[tid]       = dec[b * H_ + tid];
    dh[tid + 256] = dec[b * H_ + tid + 256];
    __syncthreads();

    const int nl = tid & 63;
    const int n  = nh * 64 + nl;
    const int ks = tid >> 6;
    float acc = 0.f;
    #pragma unroll 8
    for (int h = ks * 128; h < ks * 128 + 128; ++h)
        acc = fmaf(dh[h], Ws[(size_t)h * H_ + n], acc);
    red[ks][nl] = acc;
    __syncthreads();
    if (ks == 0) {
        float s = red[0][nl] + red[1][nl] + red[2][nl] + red[3][nl];
        g_comb[b * H_ + n] = s + bs[n] + bh[n] + bc[n];
    }
}

// ---------------------------------------------------------------------------
// Main: 128x128x512 fp16 HMMA GEMM + fused tanh/v-dot epilogue
// grid (4 nc, 1024 m-tiles), 256 threads = 8 warps (warpM 0..1 x warpN 0..3)
// warp tile 64x32; k-chunk 64; double-buffered cp.async; 2 CTAs/SM.
// ---------------------------------------------------------------------------
#define PITCH     144                     // 128B data + 16B pad -> ldmatrix conflict-free
#define MAT_BYTES (128 * PITCH)           // 18432
#define STAGE_BYTES (2 * MAT_BYTES)       // 36864 (A|B)
#define OFF_COMB  (2 * STAGE_BYTES)       // 73728
#define OFF_WC    (OFF_COMB + 512)
#define OFF_VW    (OFF_WC + 512)
#define OFF_ERED  (OFF_VW + 512)          // 75264
#define SMEM_DYN  (OFF_ERED + 128 * 16 * 4)  // 83456

__global__ __launch_bounds__(256, 2)
void attn_hmma_kernel(const float* __restrict__ cov,
                      const float* __restrict__ Wc,
                      const float* __restrict__ v_w)
{
    extern __shared__ char sm[];
    const uint32_t sbase = smem_u32(sm);
    const int tid  = threadIdx.x;
    const int wid  = tid >> 5;
    const int lane = tid & 31;
    const int nc     = blockIdx.x;          // 0..3 (fast-varying: A-tile L2 reuse)
    const int mBase  = blockIdx.y * 128;
    const int ncBase = nc * 128;
    const int b      = mBase >> 11;

    // epilogue constants for this n-chunk
    if (tid < 128) {
        ((float*)(sm + OFF_COMB))[tid] = g_comb[b * H_ + ncBase + tid];
        ((float*)(sm + OFF_WC))[tid]   = Wc[ncBase + tid];
        ((float*)(sm + OFF_VW))[tid]   = v_w[ncBase + tid];
    }

    // per-thread cp.async mapping: 2048 16B transfers/chunk, 8 per thread
    const char* srcs[8];
    uint32_t dsts[8];
    #pragma unroll
    for (int p = 0; p < 8; ++p) {
        const int idx = p * 256 + tid;
        const int mat = idx >> 10;         // 0:A 1:B
        const int r   = (idx >> 3) & 127;
        const int cc  = idx & 7;
        const __half* g = (mat == 0) ? (g_Af + (size_t)(mBase + r) * H_)
                                     : (g_Bf + (size_t)(ncBase + r) * H_);
        srcs[p] = (const char*)(g + cc * 8);
        dsts[p] = sbase + mat * MAT_BYTES + r * PITCH + cc * 16;
    }

    const int warpM = wid >> 2;            // 0..1 -> 64 rows
    const int warpN = wid & 3;             // 0..3 -> 32 cols

    // ldmatrix offsets (relative to matrix base; add stage offset later)
    uint32_t offA[4][4], offB[2][4];
    {
        const int rowA = warpM * 64 + (lane & 7) + ((lane >> 3) & 1) * 8;
        const int cA   = (lane >> 4);                   // 0..1 (16B halves of 32B step)
        #pragma unroll
        for (int mI = 0; mI < 4; ++mI)
            #pragma unroll
            for (int s = 0; s < 4; ++s)
                offA[mI][s] = (uint32_t)((rowA + mI * 16) * PITCH + (s * 2 + cA) * 16);
        const int rowB = warpN * 32 + (lane & 7) + ((lane & 16) ? 8 : 0);
        const int cB   = (lane >> 3) & 1;
        #pragma unroll
        for (int p = 0; p < 2; ++p)
            #pragma unroll
            for (int s = 0; s < 4; ++s)
                offB[p][s] = (uint32_t)((rowB + p * 16) * PITCH + (s * 2 + cB) * 16);
    }

    float acc[4][4][4];
    #pragma unroll
    for (int i = 0; i < 4; ++i)
        #pragma unroll
        for (int j = 0; j < 4; ++j)
            #pragma unroll
            for (int q = 0; q < 4; ++q) acc[i][j][q] = 0.f;

    // prefetch chunk 0
    #pragma unroll
    for (int p = 0; p < 8; ++p) cp16(dsts[p], srcs[p]);
    asm volatile("cp.async.commit_group;" ::: "memory");

    #pragma unroll 1
    for (int c = 0; c < 8; ++c) {
        if (c < 7) {
            const uint32_t soff = ((c + 1) & 1) * STAGE_BYTES;
            #pragma unroll
            for (int p = 0; p < 8; ++p)
                cp16(dsts[p] + soff, srcs[p] + (c + 1) * 128);
            asm volatile("cp.async.commit_group;" ::: "memory");
            asm volatile("cp.async.wait_group 1;" ::: "memory");
        } else {
            asm volatile("cp.async.wait_group 0;" ::: "memory");
        }
        __syncthreads();

        const uint32_t st = (c & 1) * STAGE_BYTES;
        const uint32_t ab = sbase + st;
        const uint32_t bb = ab + MAT_BYTES;

        #pragma unroll
        for (int s = 0; s < 4; ++s) {      // each s = 16 k
            uint32_t Af[4][4], Bf[2][4];
            #pragma unroll
            for (int p = 0; p < 2; ++p)    ldsm4(Bf[p], bb + offB[p][s]);
            #pragma unroll
            for (int mI = 0; mI < 4; ++mI) ldsm4(Af[mI], ab + offA[mI][s]);
            #pragma unroll
            for (int mI = 0; mI < 4; ++mI)
                #pragma unroll
                for (int nI = 0; nI < 4; ++nI)
                    mma_f16(acc[mI][nI], Af[mI], Bf[nI >> 1][(nI & 1) * 2], Bf[nI >> 1][(nI & 1) * 2 + 1]);
        }
        __syncthreads();
    }

    // ---- fused epilogue: tanh + v-dot, reduce across 16 column-threads ----
    const float* sComb = (const float*)(sm + OFF_COMB);
    const float* sWc   = (const float*)(sm + OFF_WC);
    const float* sVw   = (const float*)(sm + OFF_VW);
    float* ered = (float*)(sm + OFF_ERED);
    const int col = warpN * 4 + (lane & 3);

    #pragma unroll
    for (int mI = 0; mI < 4; ++mI) {
        const int mlo = warpM * 64 + mI * 16 + (lane >> 2);
        const float covlo = cov[mBase + mlo];
        const float covhi = cov[mBase + mlo + 8];
        float elo = 0.f, ehi = 0.f;
        #pragma unroll
        for (int nI = 0; nI < 4; ++nI) {
            #pragma unroll
            for (int t = 0; t < 2; ++t) {
                const int n = warpN * 32 + nI * 8 + (lane & 3) * 2 + t;
                const float cb = sComb[n], wc = sWc[n], vw = sVw[n];
                elo = fmaf(vw, tanh_acc(acc[mI][nI][t]     + cb + covlo * wc), elo);
                ehi = fmaf(vw, tanh_acc(acc[mI][nI][t + 2] + cb + covhi * wc), ehi);
            }
        }
        ered[mlo * 16 + col]       = elo;
        ered[(mlo + 8) * 16 + col] = ehi;
    }
    __syncthreads();
    if (tid < 128) {
        float s = 0.f;
        #pragma unroll
        for (int t = 0; t < 16; ++t) s += ered[tid * 16 + t];
        g_epart[nc * M_ + mBase + tid] = s;
    }
}

// ---------------------------------------------------------------------------
// Softmax over S=2048 per batch + coverage update (v_b shift-invariant)
// ---------------------------------------------------------------------------
__global__ __launch_bounds__(256)
void softmax_kernel(const float* __restrict__ cov, float* __restrict__ out)
{
    const int b   = blockIdx.x;
    const int tid = threadIdx.x;
    __shared__ float red[256];

    float local[8];
    float mx = -INFINITY;
    #pragma unroll
    for (int i = 0; i < 8; ++i) {
        const int idx = b * S_ + tid + i * 256;
        local[i] = g_epart[idx] + g_epart[M_ + idx] + g_epart[2 * M_ + idx] + g_epart[3 * M_ + idx];
        mx = fmaxf(mx, local[i]);
    }
    red[tid] = mx;
    __syncthreads();
    for (int s = 128; s > 0; s >>= 1) {
        if (tid < s) red[tid] = fmaxf(red[tid], red[tid + s]);
        __syncthreads();
    }
    const float m = red[0];
    __syncthreads();

    float sum = 0.f;
    #pragma unroll
    for (int i = 0; i < 8; ++i) {
        local[i] = __expf(local[i] - m);
        sum += local[i];
    }
    red[tid] = sum;
    __syncthreads();
    for (int s = 128; s > 0; s >>= 1) {
        if (tid < s) red[tid] += red[tid + s];
        __syncthreads();
    }
    const float inv = 1.0f / red[0];

    #pragma unroll
    for (int i = 0; i < 8; ++i) {
        const int idx = b * S_ + tid + i * 256;
        const float a = local[i] * inv;
        out[idx]      = a;
        out[M_ + idx] = cov[idx] + a;
    }
}

// ---------------------------------------------------------------------------
extern "C" void kernel_launch(void* const* d_in, const int* in_sizes, int n_in,
                              void* d_out, int out_size)
{
    const float* enc = (const float*)d_in[0];
    const float* dec = (const float*)d_in[1];
    const float* cov = (const float*)d_in[2];
    const float* Wh  = (const float*)d_in[3];
    const float* bh  = (const float*)d_in[4];
    const float* Ws  = (const float*)d_in[5];
    const float* bs  = (const float*)d_in[6];
    const float* Wc  = (const float*)d_in[7];
    const float* bc  = (const float*)d_in[8];
    const float* v_w = (const float*)d_in[9];
    float* out = (float*)d_out;

    cudaFuncSetAttribute(attn_hmma_kernel,
                         cudaFuncAttributeMaxDynamicSharedMemorySize, SMEM_DYN);

    apack_kernel<<<M_ * H_ / 4 / 256, 256>>>(enc);
    bpack_kernel<<<H_, 128>>>(Wh);
    dec_comb_kernel<<<dim3(B_, 8), 256>>>(dec, Ws, bs, bh, bc);
    attn_hmma_kernel<<<dim3(4, M_ / 128), 256, SMEM_DYN>>>(cov, Wc, v_w);
    softmax_kernel<<<B_, 256>>>(cov, out);
}

// round 11
// speedup vs baseline: 6.1885x; 1.1040x over previous
#include <cuda_runtime.h>
#include <cuda_fp16.h>
#include <math.h>
#include <stdint.h>

#define B_  64
#define S_  2048
#define H_  512
#define M_  (B_ * S_)

// ---------------- device scratch (no allocs allowed) ----------------
__device__ __half g_Af[(size_t)M_ * H_];   // 128 MB enc fp16
__device__ __half g_Bf[H_ * H_];           // Wh^T fp16 [n][k]
__device__ float g_comb[B_ * H_];          // dec@Ws + bs + bh + bc
__device__ float g_epart[4 * M_];          // per-nc partial e sums

// ---------------- helpers ----------------
__device__ __forceinline__ uint32_t smem_u32(const void* p) {
    uint32_t a;
    asm("{ .reg .u64 t; cvta.to.shared.u64 t, %1; cvt.u32.u64 %0, t; }" : "=r"(a) : "l"(p));
    return a;
}
// accurate tanh: 2 MUFU, rel err ~1e-7, saturates correctly
__device__ __forceinline__ float tanh_acc(float x) {
    float e = __expf(2.0f * x);
    return 1.0f - __fdividef(2.0f, e + 1.0f);
}
__device__ __forceinline__ void ldsm4(uint32_t* r, uint32_t addr) {
    asm volatile("ldmatrix.sync.aligned.m8n8.x4.shared.b16 {%0,%1,%2,%3}, [%4];"
                 : "=r"(r[0]), "=r"(r[1]), "=r"(r[2]), "=r"(r[3]) : "r"(addr));
}
__device__ __forceinline__ void mma_f16(float* c, const uint32_t* a, uint32_t b0, uint32_t b1) {
    asm volatile(
        "mma.sync.aligned.m16n8k16.row.col.f32.f16.f16.f32 "
        "{%0,%1,%2,%3},{%4,%5,%6,%7},{%8,%9},{%0,%1,%2,%3};"
        : "+f"(c[0]), "+f"(c[1]), "+f"(c[2]), "+f"(c[3])
        : "r"(a[0]), "r"(a[1]), "r"(a[2]), "r"(a[3]), "r"(b0), "r"(b1));
}
__device__ __forceinline__ void cp16(uint32_t dst, const void* src) {
    asm volatile("cp.async.cg.shared.global [%0], [%1], 16;" :: "r"(dst), "l"(src));
}

// ---------------------------------------------------------------------------
// Pack A: enc fp32 -> g_Af fp16
// ---------------------------------------------------------------------------
__global__ void apack_kernel(const float* __restrict__ A)
{
    const size_t i = (size_t)blockIdx.x * 256 + threadIdx.x;  // float4 index
    const float4 v = ((const float4*)A)[i];
    __half2 lo = __floats2half2_rn(v.x, v.y);
    __half2 hi = __floats2half2_rn(v.z, v.w);
    ((uint2*)g_Af)[i] = make_uint2(*(uint32_t*)&lo, *(uint32_t*)&hi);
}

// ---------------------------------------------------------------------------
// Pack B: Wh [k][n] fp32 -> g_Bf [n][k] fp16 (transpose)
// ---------------------------------------------------------------------------
__global__ void bpack_kernel(const float* __restrict__ Wh)
{
    const int n  = blockIdx.x;              // 0..511
    const int k4 = threadIdx.x * 4;         // 128 threads x 4 k
    __half2 lo = __floats2half2_rn(Wh[(size_t)(k4 + 0) * H_ + n], Wh[(size_t)(k4 + 1) * H_ + n]);
    __half2 hi = __floats2half2_rn(Wh[(size_t)(k4 + 2) * H_ + n], Wh[(size_t)(k4 + 3) * H_ + n]);
    *(uint2*)(g_Bf + (size_t)n * H_ + k4) = make_uint2(*(uint32_t*)&lo, *(uint32_t*)&hi);
}

// ---------------------------------------------------------------------------
// comb[b][n] = dec[b] @ Ws[:,n] + bs + bh + bc
// ---------------------------------------------------------------------------
__global__ void dec_comb_kernel(const float* __restrict__ dec,
                                const float* __restrict__ Ws,
                                const float* __restrict__ bs,
                                const float* __restrict__ bh,
                                const float* __restrict__ bc)
{
    const int b  = blockIdx.x;
    const int nh = blockIdx.y;
    const int tid = threadIdx.x;
    __shared__ float dh[H_];
    __shared__ float red[4][64];

    dh[tid]       = dec[b * H_ + tid];
    dh[tid + 256] = dec[b * H_ + tid + 256];
    __syncthreads();

    const int nl = tid & 63;
    const int n  = nh * 64 + nl;
    const int ks = tid >> 6;
    float acc = 0.f;
    #pragma unroll 8
    for (int h = ks * 128; h < ks * 128 + 128; ++h)
        acc = fmaf(dh[h], Ws[(size_t)h * H_ + n], acc);
    red[ks][nl] = acc;
    __syncthreads();
    if (ks == 0) {
        float s = red[0][nl] + red[1][nl] + red[2][nl] + red[3][nl];
        g_comb[b * H_ + n] = s + bs[n] + bh[n] + bc[n];
    }
}

// ---------------------------------------------------------------------------
// Main: 128x128x512 fp16 HMMA GEMM + fused tanh/v-dot epilogue
// grid (4 nc, 1024 m-tiles), 256 threads = 8 warps (warpM 0..1 x warpN 0..3)
// warp tile 64x32; k-chunk 64 (128B rows, XOR-swizzled); 3-stage cp.async
// pipeline with ONE __syncthreads per k-iter; 2 CTAs/SM.
// ---------------------------------------------------------------------------
#define MAT_BYTES   16384                 // 128 rows x 128B (swizzled, no pad)
#define STAGE_BYTES (2 * MAT_BYTES)       // 32768 (A|B)
#define OFF_COMB  (3 * STAGE_BYTES)       // 98304
#define OFF_WC    (OFF_COMB + 512)
#define OFF_VW    (OFF_WC + 512)
#define OFF_ERED  (OFF_VW + 512)          // 99840
#define SMEM_DYN  (OFF_ERED + 128 * 16 * 4)  // 108032

// swizzled byte offset of (row r, 16B-chunk c) within a 128x128B matrix
#define SWZOFF(r, c) ((uint32_t)((r) * 128 + (((c) ^ ((r) & 7)) << 4)))

__global__ __launch_bounds__(256, 2)
void attn_hmma_kernel(const float* __restrict__ cov,
                      const float* __restrict__ Wc,
                      const float* __restrict__ v_w)
{
    extern __shared__ char sm[];
    const uint32_t sbase = smem_u32(sm);
    const int tid  = threadIdx.x;
    const int wid  = tid >> 5;
    const int lane = tid & 31;
    const int nc     = blockIdx.x;          // 0..3 (fast-varying: A-tile L2 reuse)
    const int mBase  = blockIdx.y * 128;
    const int ncBase = nc * 128;
    const int b      = mBase >> 11;

    // epilogue constants for this n-chunk (ordered before use by iter-0 sync)
    if (tid < 128) {
        ((float*)(sm + OFF_COMB))[tid] = g_comb[b * H_ + ncBase + tid];
        ((float*)(sm + OFF_WC))[tid]   = Wc[ncBase + tid];
        ((float*)(sm + OFF_VW))[tid]   = v_w[ncBase + tid];
    }

    // per-thread cp.async mapping: 2048 16B transfers/chunk, 8 per thread
    const char* srcs[8];
    uint32_t dsts[8];                      // stage-0 destinations
    #pragma unroll
    for (int p = 0; p < 8; ++p) {
        const int idx = p * 256 + tid;
        const int mat = idx >> 10;         // 0:A 1:B
        const int r   = (idx >> 3) & 127;
        const int cc  = idx & 7;
        const __half* g = (mat == 0) ? (g_Af + (size_t)(mBase + r) * H_)
                                     : (g_Bf + (size_t)(ncBase + r) * H_);
        srcs[p] = (const char*)(g + cc * 8);
        dsts[p] = sbase + mat * MAT_BYTES + SWZOFF(r, cc);
    }

    const int warpM = wid >> 2;            // 0..1 -> 64 rows
    const int warpN = wid & 3;             // 0..3 -> 32 cols

    // ldmatrix offsets (within a matrix; add stage/mat base later)
    uint32_t offA[4][4], offB[2][4];
    {
        const int rowA = warpM * 64 + (lane & 7) + ((lane >> 3) & 1) * 8;
        const int cA   = (lane >> 4);                   // 0..1
        #pragma unroll
        for (int mI = 0; mI < 4; ++mI)
            #pragma unroll
            for (int s = 0; s < 4; ++s)
                offA[mI][s] = SWZOFF(rowA + mI * 16, s * 2 + cA);
        const int rowB = warpN * 32 + (lane & 7) + ((lane & 16) ? 8 : 0);
        const int cB   = (lane >> 3) & 1;
        #pragma unroll
        for (int p = 0; p < 2; ++p)
            #pragma unroll
            for (int s = 0; s < 4; ++s)
                offB[p][s] = SWZOFF(rowB + p * 16, s * 2 + cB);
    }

    float acc[4][4][4];
    #pragma unroll
    for (int i = 0; i < 4; ++i)
        #pragma unroll
        for (int j = 0; j < 4; ++j)
            #pragma unroll
            for (int q = 0; q < 4; ++q) acc[i][j][q] = 0.f;

    // prologue: prefetch chunks 0 and 1 into stages 0 and 1
    #pragma unroll
    for (int p = 0; p < 8; ++p) cp16(dsts[p], srcs[p]);
    asm volatile("cp.async.commit_group;" ::: "memory");
    #pragma unroll
    for (int p = 0; p < 8; ++p) cp16(dsts[p] + STAGE_BYTES, srcs[p] + 128);
    asm volatile("cp.async.commit_group;" ::: "memory");

    int rdStage = 0;   // c % 3
    int wrStage = 2;   // (c+2) % 3
    #pragma unroll 1
    for (int c = 0; c < 8; ++c) {
        // chunk c guaranteed complete (groups complete in commit order)
        if (c < 7) asm volatile("cp.async.wait_group 1;" ::: "memory");
        else       asm volatile("cp.async.wait_group 0;" ::: "memory");
        __syncthreads();   // single barrier per iteration

        const uint32_t ab = sbase + rdStage * STAGE_BYTES;
        const uint32_t bb = ab + MAT_BYTES;

        #pragma unroll
        for (int s = 0; s < 4; ++s) {      // each s = 16 k
            uint32_t Af[4][4], Bf[2][4];
            #pragma unroll
            for (int p = 0; p < 2; ++p)    ldsm4(Bf[p], bb + offB[p][s]);
            #pragma unroll
            for (int mI = 0; mI < 4; ++mI) ldsm4(Af[mI], ab + offA[mI][s]);
            #pragma unroll
            for (int mI = 0; mI < 4; ++mI)
                #pragma unroll
                for (int nI = 0; nI < 4; ++nI)
                    mma_f16(acc[mI][nI], Af[mI], Bf[nI >> 1][(nI & 1) * 2], Bf[nI >> 1][(nI & 1) * 2 + 1]);
        }

        // prefetch chunk c+2 into wrStage = (c+2)%3 (safe: no reader left on it)
        if (c + 2 < 8) {
            const uint32_t soff = (uint32_t)wrStage * STAGE_BYTES;
            const int koff = (c + 2) * 128;
            #pragma unroll
            for (int p = 0; p < 8; ++p)
                cp16(dsts[p] + soff, srcs[p] + koff);
            asm volatile("cp.async.commit_group;" ::: "memory");
        }

        rdStage = (rdStage == 2) ? 0 : rdStage + 1;
        wrStage = (wrStage == 2) ? 0 : wrStage + 1;
    }

    // ---- fused epilogue: tanh + v-dot, reduce across 16 column-threads ----
    const float* sComb = (const float*)(sm + OFF_COMB);
    const float* sWc   = (const float*)(sm + OFF_WC);
    const float* sVw   = (const float*)(sm + OFF_VW);
    float* ered = (float*)(sm + OFF_ERED);
    const int col = warpN * 4 + (lane & 3);

    #pragma unroll
    for (int mI = 0; mI < 4; ++mI) {
        const int mlo = warpM * 64 + mI * 16 + (lane >> 2);
        const float covlo = cov[mBase + mlo];
        const float covhi = cov[mBase + mlo + 8];
        float elo = 0.f, ehi = 0.f;
        #pragma unroll
        for (int nI = 0; nI < 4; ++nI) {
            #pragma unroll
            for (int t = 0; t < 2; ++t) {
                const int n = warpN * 32 + nI * 8 + (lane & 3) * 2 + t;
                const float cb = sComb[n], wc = sWc[n], vw = sVw[n];
                elo = fmaf(vw, tanh_acc(acc[mI][nI][t]     + cb + covlo * wc), elo);
                ehi = fmaf(vw, tanh_acc(acc[mI][nI][t + 2] + cb + covhi * wc), ehi);
            }
        }
        ered[mlo * 16 + col]       = elo;
        ered[(mlo + 8) * 16 + col] = ehi;
    }
    __syncthreads();
    if (tid < 128) {
        float s = 0.f;
        #pragma unroll
        for (int t = 0; t < 16; ++t) s += ered[tid * 16 + t];
        g_epart[nc * M_ + mBase + tid] = s;
    }
}

// ---------------------------------------------------------------------------
// Softmax over S=2048 per batch + coverage update (v_b shift-invariant)
// ---------------------------------------------------------------------------
__global__ __launch_bounds__(256)
void softmax_kernel(const float* __restrict__ cov, float* __restrict__ out)
{
    const int b   = blockIdx.x;
    const int tid = threadIdx.x;
    __shared__ float red[256];

    float local[8];
    float mx = -INFINITY;
    #pragma unroll
    for (int i = 0; i < 8; ++i) {
        const int idx = b * S_ + tid + i * 256;
        local[i] = g_epart[idx] + g_epart[M_ + idx] + g_epart[2 * M_ + idx] + g_epart[3 * M_ + idx];
        mx = fmaxf(mx, local[i]);
    }
    red[tid] = mx;
    __syncthreads();
    for (int s = 128; s > 0; s >>= 1) {
        if (tid < s) red[tid] = fmaxf(red[tid], red[tid + s]);
        __syncthreads();
    }
    const float m = red[0];
    __syncthreads();

    float sum = 0.f;
    #pragma unroll
    for (int i = 0; i < 8; ++i) {
        local[i] = __expf(local[i] - m);
        sum += local[i];
    }
    red[tid] = sum;
    __syncthreads();
    for (int s = 128; s > 0; s >>= 1) {
        if (tid < s) red[tid] += red[tid + s];
        __syncthreads();
    }
    const float inv = 1.0f / red[0];

    #pragma unroll
    for (int i = 0; i < 8; ++i) {
        const int idx = b * S_ + tid + i * 256;
        const float a = local[i] * inv;
        out[idx]      = a;
        out[M_ + idx] = cov[idx] + a;
    }
}

// ---------------------------------------------------------------------------
extern "C" void kernel_launch(void* const* d_in, const int* in_sizes, int n_in,
                              void* d_out, int out_size)
{
    const float* enc = (const float*)d_in[0];
    const float* dec = (const float*)d_in[1];
    const float* cov = (const float*)d_in[2];
    const float* Wh  = (const float*)d_in[3];
    const float* bh  = (const float*)d_in[4];
    const float* Ws  = (const float*)d_in[5];
    const float* bs  = (const float*)d_in[6];
    const float* Wc  = (const float*)d_in[7];
    const float* bc  = (const float*)d_in[8];
    const float* v_w = (const float*)d_in[9];
    float* out = (float*)d_out;

    cudaFuncSetAttribute(attn_hmma_kernel,
                         cudaFuncAttributeMaxDynamicSharedMemorySize, SMEM_DYN);

    apack_kernel<<<M_ * H_ / 4 / 256, 256>>>(enc);
    bpack_kernel<<<H_, 128>>>(Wh);
    dec_comb_kernel<<<dim3(B_, 8), 256>>>(dec, Ws, bs, bh, bc);
    attn_hmma_kernel<<<dim3(4, M_ / 128), 256, SMEM_DYN>>>(cov, Wc, v_w);
    softmax_kernel<<<B_, 256>>>(cov, out);
}